// round 9
// baseline (speedup 1.0000x reference)
#include <cuda_runtime.h>
#include <cstdint>

#define TT 512
#define DD 256
#define LL 256
#define HH 512
#define ZDIM 1024
#define CLU 8    // CTAs per cluster = per LSTM direction

// ---------------- device scratch (no allocations allowed) ----------------
__device__ __align__(16) float g_xw_a[TT * ZDIM];
__device__ __align__(16) float g_xw_b[TT * ZDIM];
__device__ __align__(16) float g_Ut[4][ZDIM * LL];   // transposed U: [col = gate*256+u][k]
__device__ __align__(16) float g_v[TT * 2 * LL];     // layer-1 bilstm output (concat layout)
__device__ __align__(16) float g_hcat[TT * 2 * LL];  // layer-2 bilstm output (concat layout)
__device__ __align__(16) float g_headf[TT * HH];
__device__ __align__(16) float g_modf[TT * HH];

// ---------------- fast activations ----------------
__device__ __forceinline__ float fsig(float x) {     // rel err ~1e-6 (exp-based; used in LSTM)
    float e = __expf(-x);
    return __fdividef(1.f, 1.f + e);
}
__device__ __forceinline__ float ftanh(float x) {    // rel err ~1e-6 (exp-based; used in LSTM)
    float e = __expf(2.f * x);
    return 1.f - __fdividef(2.f, e + 1.f);
}
__device__ __forceinline__ float ftanh_hw(float x) { // MUFU tanh (head only; errors average out)
    float r;
    asm("tanh.approx.f32 %0, %1;" : "=f"(r) : "f"(x));
    return r;
}

__device__ __forceinline__ uint32_t smem_u32(const void* p) {
    uint32_t a;
    asm("{ .reg .u64 t; cvta.to.shared.u64 t, %1; cvt.u32.u64 %0, t; }" : "=r"(a) : "l"(p));
    return a;
}

// try_wait parity with sleep (acquire)
__device__ __forceinline__ void mbar_wait_parity(uint32_t mbar, uint32_t parity) {
    uint32_t done;
    asm volatile(
        "{\n\t"
        ".reg .pred p;\n\t"
        "mbarrier.try_wait.parity.acquire.cta.shared::cta.b64 p, [%1], %2;\n\t"
        "selp.b32 %0, 1, 0, p;\n\t"
        "}"
        : "=r"(done) : "r"(mbar), "r"(parity) : "memory");
    if (!done) {
        asm volatile(
            "{\n\t"
            ".reg .pred P1;\n\t"
            "WAIT_LOOP_%=:\n\t"
            "mbarrier.try_wait.parity.acquire.cta.shared::cta.b64 P1, [%0], %1, 0x989680;\n\t"
            "@P1 bra.uni WAIT_DONE_%=;\n\t"
            "bra.uni WAIT_LOOP_%=;\n\t"
            "WAIT_DONE_%=:\n\t"
            "}"
            :: "r"(mbar), "r"(parity) : "memory");
    }
}

__device__ __forceinline__ void mbar_arrive(uint32_t mbar) {
    asm volatile("mbarrier.arrive.shared.b64 _, [%0];" :: "r"(mbar) : "memory");
}
__device__ __forceinline__ void mbar_arrive_expect(uint32_t mbar, uint32_t bytes) {
    asm volatile("mbarrier.arrive.expect_tx.shared.b64 _, [%0], %1;" :: "r"(mbar), "r"(bytes) : "memory");
}

// ---------------- U transpose: [256,1024] -> [1024,256] x4 ----------------
__global__ void transposeU_kernel(const float* __restrict__ u0, const float* __restrict__ u1,
                                  const float* __restrict__ u2, const float* __restrict__ u3) {
    __shared__ float tile[32][33];
    const float* src = (blockIdx.z == 0) ? u0 : (blockIdx.z == 1) ? u1 : (blockIdx.z == 2) ? u2 : u3;
    float* dst = g_Ut[blockIdx.z];
    int j  = blockIdx.x * 32 + threadIdx.x;   // column in U (0..1023)
    int k0 = blockIdx.y * 32;                 // row chunk (0..255)
#pragma unroll
    for (int r = 0; r < 32; r += 8)
        tile[threadIdx.y + r][threadIdx.x] = src[(k0 + threadIdx.y + r) * ZDIM + j];
    __syncthreads();
    int k  = k0 + threadIdx.x;
    int jo = blockIdx.x * 32;
#pragma unroll
    for (int r = 0; r < 32; r += 8)
        dst[(jo + threadIdx.y + r) * LL + k] = tile[threadIdx.x][threadIdx.y + r];
}

// ---------------- dual fp32 tiled GEMM: Cz = A @ Bz (+biasz), z = blockIdx.z ----------------
__global__ void __launch_bounds__(256) gemm2_kernel(
    const float* __restrict__ A0, const float* __restrict__ A1,
    const float* __restrict__ B0, const float* __restrict__ B1,
    const float* __restrict__ bias0, const float* __restrict__ bias1,
    float* __restrict__ C0, float* __restrict__ C1,
    int M, int N, int K) {
    const float* A    = (blockIdx.z == 0) ? A0 : A1;
    const float* B    = (blockIdx.z == 0) ? B0 : B1;
    const float* bias = (blockIdx.z == 0) ? bias0 : bias1;
    float* C          = (blockIdx.z == 0) ? C0 : C1;

    __shared__ __align__(16) float As[16][68];
    __shared__ __align__(16) float Bs[16][68];
    const int tid = threadIdx.x;
    const int tx = tid & 15, ty = tid >> 4;
    const int bm = blockIdx.y * 64, bn = blockIdx.x * 64;

    float acc[4][4];
#pragma unroll
    for (int i = 0; i < 4; i++)
#pragma unroll
        for (int j = 0; j < 4; j++) acc[i][j] = 0.f;

    for (int k0 = 0; k0 < K; k0 += 16) {
        {
            int ar = tid >> 2;            // 0..63
            int ac = (tid & 3) * 4;       // 0,4,8,12
            float4 av = *(const float4*)&A[(bm + ar) * K + k0 + ac];
            As[ac + 0][ar] = av.x; As[ac + 1][ar] = av.y;
            As[ac + 2][ar] = av.z; As[ac + 3][ar] = av.w;
        }
        {
            int br = tid >> 4;            // 0..15
            int bc = (tid & 15) * 4;      // 0..60
            *(float4*)&Bs[br][bc] = *(const float4*)&B[(k0 + br) * N + bn + bc];
        }
        __syncthreads();
#pragma unroll
        for (int kk = 0; kk < 16; kk++) {
            float4 a4 = *(const float4*)&As[kk][ty * 4];
            float4 b4 = *(const float4*)&Bs[kk][tx * 4];
            acc[0][0] += a4.x * b4.x; acc[0][1] += a4.x * b4.y; acc[0][2] += a4.x * b4.z; acc[0][3] += a4.x * b4.w;
            acc[1][0] += a4.y * b4.x; acc[1][1] += a4.y * b4.y; acc[1][2] += a4.y * b4.z; acc[1][3] += a4.y * b4.w;
            acc[2][0] += a4.z * b4.x; acc[2][1] += a4.z * b4.y; acc[2][2] += a4.z * b4.z; acc[2][3] += a4.z * b4.w;
            acc[3][0] += a4.w * b4.x; acc[3][1] += a4.w * b4.y; acc[3][2] += a4.w * b4.z; acc[3][3] += a4.w * b4.w;
        }
        __syncthreads();
    }
#pragma unroll
    for (int i = 0; i < 4; i++) {
        int row = bm + ty * 4 + i;
#pragma unroll
        for (int j = 0; j < 4; j++) {
            int col = bn + tx * 4 + j;
            float v = acc[i][j];
            if (bias) v += bias[col];
            C[row * N + col] = v;
        }
    }
}

// ---------------- cluster LSTM: one 8-CTA cluster per direction ----------------
// grid = 16 CTAs (2 clusters). 256 threads/CTA. U held in registers.
// Per-step sync = st.async b32 (data + tx fused) + mbarrier with arrival
// count 256: every thread arrives right after its wait (tid0 arrives with
// expect_tx) — no __syncthreads in the loop, warps run autonomously.
// Safety: remote tx into barrier b are gated by OUR warp-0 producer store,
// which follows tid0's arrive.expect_tx in program order.
__global__ void __launch_bounds__(256, 1) __cluster_dims__(CLU, 1, 1)
lstm_cluster_kernel(int layer) {
    const int dir = blockIdx.x / CLU;     // 0 = forward, 1 = backward
    uint32_t rank;
    asm("mov.u32 %0, %%cluster_ctarank;" : "=r"(rank));

    const float* xw = (dir == 0) ? g_xw_a : g_xw_b;
    const float* Ut = g_Ut[layer * 2 + dir];
    float* out = (layer == 0) ? g_v : g_hcat;
    const int coloff = dir * LL;          // concat column offset

    const int tid  = threadIdx.x;
    const int warp = tid >> 5, lane = tid & 31;
    const int usub = lane >> 3, sl = lane & 7;
    const int u = rank * 32 + warp * 4 + usub;  // hidden unit owned by this lane-group
    const bool prod = (sl == 0);                // lanes 0,8,16,24

    __shared__ __align__(16) float h_s[2][LL];
    __shared__ __align__(8) unsigned long long mbar[2];

    // Load this thread's U slice into registers: 4 gates x 8 float4 = 128 regs
    float4 Ug[4][8];
#pragma unroll
    for (int g = 0; g < 4; g++)
#pragma unroll
        for (int j = 0; j < 8; j++)
            Ug[g][j] = *(const float4*)&Ut[(g * LL + u) * LL + j * 32 + sl * 4];

    const uint32_t bar0 = smem_u32(&mbar[0]);
    const uint32_t bar1 = smem_u32(&mbar[1]);

    // init: zero h buffer 0, init barriers with arrival count 256
    h_s[0][tid] = 0.f;
    if (tid == 0) {
        asm volatile("mbarrier.init.shared.b64 [%0], 256;" :: "r"(bar0) : "memory");
        asm volatile("mbarrier.init.shared.b64 [%0], 256;" :: "r"(bar1) : "memory");
    }
    __syncthreads();
    // prime phase 0 of both barriers: 256 arrivals each; tid0 carries expect_tx
    if (tid == 0) {
        mbar_arrive_expect(bar0, LL * 4);
        mbar_arrive_expect(bar1, LL * 4);
    } else {
        mbar_arrive(bar0);
        mbar_arrive(bar1);
    }
    // barriers + zeroed h must be visible cluster-wide before any st.async lands
    asm volatile("barrier.cluster.arrive.aligned;" ::: "memory");
    asm volatile("barrier.cluster.wait.aligned;" ::: "memory");

    // hoisted DSMEM addressing: base = remote &h_s[0][u]; barrier/buffer deltas
    // are constant within-window offsets (mapa is offset-preserving).
    const uint32_t h0u = smem_u32(&h_s[0][u]);
    uint32_t dH0[CLU];
#pragma unroll
    for (int r = 0; r < CLU; r++)
        asm("mapa.shared::cluster.u32 %0, %1, %2;" : "=r"(dH0[r]) : "r"(h0u), "r"(r));
    const uint32_t offB0 = bar0 - h0u;
    const uint32_t offB1 = bar1 - h0u;
    const uint32_t offH1 = (uint32_t)(LL * 4);

    float c = 0.f;
    uint32_t ph0 = 0, ph1 = 0;   // phase parity per barrier

    // prefetch xw for the first token
    const int tok0 = (dir == 0) ? 0 : (TT - 1);
    float xwv0 = 0.f, xwv1 = 0.f, xwv2 = 0.f, xwv3 = 0.f;
    if (prod) {
        const float* xp = &xw[tok0 * ZDIM + u];
        xwv0 = __ldg(xp + 0 * LL);
        xwv1 = __ldg(xp + 1 * LL);
        xwv2 = __ldg(xp + 2 * LL);
        xwv3 = __ldg(xp + 3 * LL);
    }

    for (int s = 0; s < TT; s++) {
        if (s > 0) {
            const uint32_t b = (s & 1) ? bar1 : bar0;
            uint32_t& ph = (s & 1) ? ph1 : ph0;
            mbar_wait_parity(b, ph);
            ph ^= 1;
            // re-arm for this barrier's next use (step s+2): per-thread arrival;
            // tid0 carries the expect_tx. Precedes this thread's own stores.
            if (tid == 0) mbar_arrive_expect(b, LL * 4);
            else          mbar_arrive(b);
        }

        const float* hc = h_s[s & 1];
        const int tok = (dir == 0) ? s : (TT - 1 - s);

        float acc0 = 0.f, acc1 = 0.f, acc2 = 0.f, acc3 = 0.f;
#pragma unroll
        for (int j = 0; j < 8; j++) {
            float4 h4 = *(const float4*)&hc[j * 32 + sl * 4];
            float4 a;
            a = Ug[0][j]; acc0 += a.x * h4.x + a.y * h4.y + a.z * h4.z + a.w * h4.w;
            a = Ug[1][j]; acc1 += a.x * h4.x + a.y * h4.y + a.z * h4.z + a.w * h4.w;
            a = Ug[2][j]; acc2 += a.x * h4.x + a.y * h4.y + a.z * h4.z + a.w * h4.w;
            a = Ug[3][j]; acc3 += a.x * h4.x + a.y * h4.y + a.z * h4.z + a.w * h4.w;
        }
        // reduce across the 8 slices of this unit (lanes usub*8 .. usub*8+7)
#pragma unroll
        for (int off = 4; off; off >>= 1) {
            acc0 += __shfl_down_sync(0xffffffffu, acc0, off, 8);
            acc1 += __shfl_down_sync(0xffffffffu, acc1, off, 8);
            acc2 += __shfl_down_sync(0xffffffffu, acc2, off, 8);
            acc3 += __shfl_down_sync(0xffffffffu, acc3, off, 8);
        }

        if (prod) {
            float iv = fsig(acc0 + xwv0);
            float fv = fsig(acc1 + xwv1);
            float gv = ftanh(acc2 + xwv2);
            float ov = fsig(acc3 + xwv3);
            c = fv * c + iv * gv;
            float hv = ov * ftanh(c);

            if (s + 1 < TT) {
                // push h to next-step buffer + barrier in all 8 CTAs first
                // (starts the DSMEM flight as early as possible)
                const uint32_t q = (s + 1) & 1;
                const uint32_t offH = q ? offH1 : 0u;
                const uint32_t offB = q ? offB1 : offB0;
                const uint32_t bits = __float_as_uint(hv);
#pragma unroll
                for (int r = 0; r < CLU; r++) {
                    asm volatile(
                        "st.async.shared::cluster.mbarrier::complete_tx::bytes.b32 [%0], %1, [%2];"
                        :: "r"(dH0[r] + offH), "r"(bits), "r"(dH0[r] + offB) : "memory");
                }
            }

            out[tok * (2 * LL) + coloff + u] = hv;

            if (s + 1 < TT) {
                // prefetch next token's xw while the cluster syncs
                const int ntok = (dir == 0) ? (s + 1) : (TT - 2 - s);
                const float* xp = &xw[ntok * ZDIM + u];
                xwv0 = __ldg(xp + 0 * LL);
                xwv1 = __ldg(xp + 1 * LL);
                xwv2 = __ldg(xp + 2 * LL);
                xwv3 = __ldg(xp + 3 * LL);
            }
        }
    }

    // hygiene: no CTA exits while peers could still address its SMEM
    asm volatile("barrier.cluster.arrive.aligned;" ::: "memory");
    asm volatile("barrier.cluster.wait.aligned;" ::: "memory");
}

// ---------------- pairwise head: out[i,j] = sum_h w[h]*tanh(hf[i,h]+mf[j,h]) + ob ----------------
__global__ void __launch_bounds__(256) pairwise_kernel(
    const float* __restrict__ headf, const float* __restrict__ modf,
    const float* __restrict__ outW, const float* __restrict__ outB,
    float* __restrict__ out) {
    __shared__ __align__(16) float SH[32][132];
    __shared__ float SMt[128][33];
    __shared__ __align__(16) float Wsh[128];

    const int t = threadIdx.x;
    const int i0 = blockIdx.y * 32, j0 = blockIdx.x * 32;
    const int li = t >> 3;
    const int lj = (t & 7) * 4;

    float acc0 = 0.f, acc1 = 0.f, acc2 = 0.f, acc3 = 0.f;

    for (int hc = 0; hc < HH; hc += 128) {
#pragma unroll
        for (int r = 0; r < 4; r++) {
            int idx = t + r * 256;
            int row = idx >> 5;
            int c4 = (idx & 31) * 4;
            float4 hvv = *(const float4*)&headf[(i0 + row) * HH + hc + c4];
            *(float4*)&SH[row][c4] = hvv;
            float4 mvv = *(const float4*)&modf[(j0 + row) * HH + hc + c4];
            SMt[c4 + 0][row] = mvv.x; SMt[c4 + 1][row] = mvv.y;
            SMt[c4 + 2][row] = mvv.z; SMt[c4 + 3][row] = mvv.w;
        }
        if (t < 32) *(float4*)&Wsh[t * 4] = *(const float4*)&outW[hc + t * 4];
        __syncthreads();

#pragma unroll 4
        for (int h = 0; h < 128; h++) {
            float hv = SH[li][h];
            float w = Wsh[h];
            acc0 += w * ftanh_hw(hv + SMt[h][lj + 0]);
            acc1 += w * ftanh_hw(hv + SMt[h][lj + 1]);
            acc2 += w * ftanh_hw(hv + SMt[h][lj + 2]);
            acc3 += w * ftanh_hw(hv + SMt[h][lj + 3]);
        }
        __syncthreads();
    }

    const float ob = outB[0];
    float* orow = &out[(i0 + li) * TT + j0 + lj];
    orow[0] = acc0 + ob;
    orow[1] = acc1 + ob;
    orow[2] = acc2 + ob;
    orow[3] = acc3 + ob;
}

// ---------------- host side ----------------
extern "C" void kernel_launch(void* const* d_in, const int* in_sizes, int n_in,
                              void* d_out, int out_size) {
    (void)in_sizes; (void)n_in; (void)out_size;
    const float* emb     = (const float*)d_in[0];
    const float* W_f1    = (const float*)d_in[1];
    const float* U_f1    = (const float*)d_in[2];
    const float* b_f1    = (const float*)d_in[3];
    const float* W_b1    = (const float*)d_in[4];
    const float* U_b1    = (const float*)d_in[5];
    const float* b_b1    = (const float*)d_in[6];
    const float* W_f2    = (const float*)d_in[7];
    const float* U_f2    = (const float*)d_in[8];
    const float* b_f2    = (const float*)d_in[9];
    const float* W_b2    = (const float*)d_in[10];
    const float* U_b2    = (const float*)d_in[11];
    const float* b_b2    = (const float*)d_in[12];
    const float* FOH     = (const float*)d_in[13];
    const float* FOM     = (const float*)d_in[14];
    const float* hidBias = (const float*)d_in[15];
    const float* outW    = (const float*)d_in[16];
    const float* outBias = (const float*)d_in[17];

    float *xwa, *xwb, *v, *hcat, *headf, *modf;
    cudaGetSymbolAddress((void**)&xwa,   g_xw_a);
    cudaGetSymbolAddress((void**)&xwb,   g_xw_b);
    cudaGetSymbolAddress((void**)&v,     g_v);
    cudaGetSymbolAddress((void**)&hcat,  g_hcat);
    cudaGetSymbolAddress((void**)&headf, g_headf);
    cudaGetSymbolAddress((void**)&modf,  g_modf);

    // 1. transpose all recurrent matrices
    transposeU_kernel<<<dim3(ZDIM / 32, LL / 32, 4), dim3(32, 8)>>>(U_f1, U_b1, U_f2, U_b2);

    // 2. layer-1 input projections (both directions, bias folded in)
    gemm2_kernel<<<dim3(ZDIM / 64, TT / 64, 2), 256>>>(
        emb, emb, W_f1, W_b1, b_f1, b_b1, xwa, xwb, TT, ZDIM, DD);

    // 3. layer-1 BiLSTM (fw + bw clusters concurrently), writes concat layout -> v
    lstm_cluster_kernel<<<2 * CLU, 256>>>(0);

    // 4. layer-2 input projections
    gemm2_kernel<<<dim3(ZDIM / 64, TT / 64, 2), 256>>>(
        v, v, W_f2, W_b2, b_f2, b_b2, xwa, xwb, TT, ZDIM, 2 * LL);

    // 5. layer-2 BiLSTM -> hcat
    lstm_cluster_kernel<<<2 * CLU, 256>>>(1);

    // 6. head projections (hidBias folded into headfov)
    gemm2_kernel<<<dim3(HH / 64, TT / 64, 2), 256>>>(
        hcat, hcat, FOH, FOM, hidBias, nullptr, headf, modf, TT, HH, 2 * LL);

    // 7. pairwise scores
    pairwise_kernel<<<dim3(TT / 32, TT / 32), 256>>>(headf, modf, outW, outBias, (float*)d_out);
}

// round 10
// speedup vs baseline: 1.0120x; 1.0120x over previous
#include <cuda_runtime.h>
#include <cstdint>

#define TT 512
#define DD 256
#define LL 256
#define HH 512
#define ZDIM 1024
#define CLU 8    // CTAs per cluster = per LSTM direction

// ---------------- device scratch (no allocations allowed) ----------------
__device__ __align__(16) float g_xw_a[TT * ZDIM];
__device__ __align__(16) float g_xw_b[TT * ZDIM];
__device__ __align__(16) float g_Ut[4][ZDIM * LL];   // transposed U: [col = gate*256+u][k]
__device__ __align__(16) float g_v[TT * 2 * LL];     // layer-1 bilstm output (concat layout)
__device__ __align__(16) float g_hcat[TT * 2 * LL];  // layer-2 bilstm output (concat layout)
__device__ __align__(16) float g_headf[TT * HH];
__device__ __align__(16) float g_modf[TT * HH];

// ---------------- fast activations ----------------
__device__ __forceinline__ float fsig(float x) {     // rel err ~1e-6 (exp-based; used in LSTM)
    float e = __expf(-x);
    return __fdividef(1.f, 1.f + e);
}
__device__ __forceinline__ float ftanh(float x) {    // rel err ~1e-6 (exp-based; used in LSTM)
    float e = __expf(2.f * x);
    return 1.f - __fdividef(2.f, e + 1.f);
}
__device__ __forceinline__ float ftanh_hw(float x) { // MUFU tanh (head only; errors average out)
    float r;
    asm("tanh.approx.f32 %0, %1;" : "=f"(r) : "f"(x));
    return r;
}

__device__ __forceinline__ uint32_t smem_u32(const void* p) {
    uint32_t a;
    asm("{ .reg .u64 t; cvta.to.shared.u64 t, %1; cvt.u32.u64 %0, t; }" : "=r"(a) : "l"(p));
    return a;
}

// try_wait parity with sleep (acquire)
__device__ __forceinline__ void mbar_wait_parity(uint32_t mbar, uint32_t parity) {
    uint32_t done;
    asm volatile(
        "{\n\t"
        ".reg .pred p;\n\t"
        "mbarrier.try_wait.parity.acquire.cta.shared::cta.b64 p, [%1], %2;\n\t"
        "selp.b32 %0, 1, 0, p;\n\t"
        "}"
        : "=r"(done) : "r"(mbar), "r"(parity) : "memory");
    if (!done) {
        asm volatile(
            "{\n\t"
            ".reg .pred P1;\n\t"
            "WAIT_LOOP_%=:\n\t"
            "mbarrier.try_wait.parity.acquire.cta.shared::cta.b64 P1, [%0], %1, 0x989680;\n\t"
            "@P1 bra.uni WAIT_DONE_%=;\n\t"
            "bra.uni WAIT_LOOP_%=;\n\t"
            "WAIT_DONE_%=:\n\t"
            "}"
            :: "r"(mbar), "r"(parity) : "memory");
    }
}

// ---------------- U transpose: [256,1024] -> [1024,256] x4 ----------------
__global__ void transposeU_kernel(const float* __restrict__ u0, const float* __restrict__ u1,
                                  const float* __restrict__ u2, const float* __restrict__ u3) {
    __shared__ float tile[32][33];
    const float* src = (blockIdx.z == 0) ? u0 : (blockIdx.z == 1) ? u1 : (blockIdx.z == 2) ? u2 : u3;
    float* dst = g_Ut[blockIdx.z];
    int j  = blockIdx.x * 32 + threadIdx.x;   // column in U (0..1023)
    int k0 = blockIdx.y * 32;                 // row chunk (0..255)
#pragma unroll
    for (int r = 0; r < 32; r += 8)
        tile[threadIdx.y + r][threadIdx.x] = src[(k0 + threadIdx.y + r) * ZDIM + j];
    __syncthreads();
    int k  = k0 + threadIdx.x;
    int jo = blockIdx.x * 32;
#pragma unroll
    for (int r = 0; r < 32; r += 8)
        dst[(jo + threadIdx.y + r) * LL + k] = tile[threadIdx.x][threadIdx.y + r];
}

// ---------------- dual fp32 tiled GEMM, double-buffered smem ----------------
// Cz = A @ Bz (+biasz), z = blockIdx.z. One __syncthreads per k-block; the
// next block's global loads are in flight during compute on the current one.
__global__ void __launch_bounds__(256) gemm2_kernel(
    const float* __restrict__ A0, const float* __restrict__ A1,
    const float* __restrict__ B0, const float* __restrict__ B1,
    const float* __restrict__ bias0, const float* __restrict__ bias1,
    float* __restrict__ C0, float* __restrict__ C1,
    int M, int N, int K) {
    const float* A    = (blockIdx.z == 0) ? A0 : A1;
    const float* B    = (blockIdx.z == 0) ? B0 : B1;
    const float* bias = (blockIdx.z == 0) ? bias0 : bias1;
    float* C          = (blockIdx.z == 0) ? C0 : C1;

    __shared__ __align__(16) float As[2][16][68];
    __shared__ __align__(16) float Bs[2][16][68];
    const int tid = threadIdx.x;
    const int tx = tid & 15, ty = tid >> 4;
    const int bm = blockIdx.y * 64, bn = blockIdx.x * 64;

    const int ar = tid >> 2;            // A row 0..63
    const int ac = (tid & 3) * 4;       // A col 0,4,8,12
    const int br = tid >> 4;            // B row 0..15
    const int bc = (tid & 15) * 4;      // B col 0..60

    float acc[4][4];
#pragma unroll
    for (int i = 0; i < 4; i++)
#pragma unroll
        for (int j = 0; j < 4; j++) acc[i][j] = 0.f;

    // prologue: block 0 -> buffer 0
    {
        float4 av = *(const float4*)&A[(bm + ar) * K + ac];
        As[0][ac + 0][ar] = av.x; As[0][ac + 1][ar] = av.y;
        As[0][ac + 2][ar] = av.z; As[0][ac + 3][ar] = av.w;
        float4 bv = *(const float4*)&B[br * N + bn + bc];
        *(float4*)&Bs[0][br][bc] = bv;
    }
    __syncthreads();

    int p = 0;
    for (int k0 = 16; k0 < K; k0 += 16) {
        // issue next block's global loads early
        float4 av = *(const float4*)&A[(bm + ar) * K + k0 + ac];
        float4 bv = *(const float4*)&B[(k0 + br) * N + bn + bc];

        // compute on buffer p
        {
            const float (*Ac)[68] = As[p];
            const float (*Bc)[68] = Bs[p];
#pragma unroll
            for (int kk = 0; kk < 16; kk++) {
                float4 a4 = *(const float4*)&Ac[kk][ty * 4];
                float4 b4 = *(const float4*)&Bc[kk][tx * 4];
                acc[0][0] += a4.x * b4.x; acc[0][1] += a4.x * b4.y; acc[0][2] += a4.x * b4.z; acc[0][3] += a4.x * b4.w;
                acc[1][0] += a4.y * b4.x; acc[1][1] += a4.y * b4.y; acc[1][2] += a4.y * b4.z; acc[1][3] += a4.y * b4.w;
                acc[2][0] += a4.z * b4.x; acc[2][1] += a4.z * b4.y; acc[2][2] += a4.z * b4.z; acc[2][3] += a4.z * b4.w;
                acc[3][0] += a4.w * b4.x; acc[3][1] += a4.w * b4.y; acc[3][2] += a4.w * b4.z; acc[3][3] += a4.w * b4.w;
            }
        }

        // store staged block into the other buffer
        p ^= 1;
        As[p][ac + 0][ar] = av.x; As[p][ac + 1][ar] = av.y;
        As[p][ac + 2][ar] = av.z; As[p][ac + 3][ar] = av.w;
        *(float4*)&Bs[p][br][bc] = bv;
        __syncthreads();
    }

    // epilogue: compute on the last buffer
    {
        const float (*Ac)[68] = As[p];
        const float (*Bc)[68] = Bs[p];
#pragma unroll
        for (int kk = 0; kk < 16; kk++) {
            float4 a4 = *(const float4*)&Ac[kk][ty * 4];
            float4 b4 = *(const float4*)&Bc[kk][tx * 4];
            acc[0][0] += a4.x * b4.x; acc[0][1] += a4.x * b4.y; acc[0][2] += a4.x * b4.z; acc[0][3] += a4.x * b4.w;
            acc[1][0] += a4.y * b4.x; acc[1][1] += a4.y * b4.y; acc[1][2] += a4.y * b4.z; acc[1][3] += a4.y * b4.w;
            acc[2][0] += a4.z * b4.x; acc[2][1] += a4.z * b4.y; acc[2][2] += a4.z * b4.z; acc[2][3] += a4.z * b4.w;
            acc[3][0] += a4.w * b4.x; acc[3][1] += a4.w * b4.y; acc[3][2] += a4.w * b4.z; acc[3][3] += a4.w * b4.w;
        }
    }

#pragma unroll
    for (int i = 0; i < 4; i++) {
        int row = bm + ty * 4 + i;
#pragma unroll
        for (int j = 0; j < 4; j++) {
            int col = bn + tx * 4 + j;
            float v = acc[i][j];
            if (bias) v += bias[col];
            C[row * N + col] = v;
        }
    }
}

// ---------------- cluster LSTM: one 8-CTA cluster per direction ----------------
// (exact R8 form: proven 784.9us) grid = 16 CTAs (2 clusters). 256 threads/CTA.
// U in registers; per-step sync = st.async b32 + count-1 mbarrier parity wait,
// tid0 re-arm + __syncthreads; mapa addressing hoisted.
__global__ void __launch_bounds__(256, 1) __cluster_dims__(CLU, 1, 1)
lstm_cluster_kernel(int layer) {
    const int dir = blockIdx.x / CLU;     // 0 = forward, 1 = backward
    uint32_t rank;
    asm("mov.u32 %0, %%cluster_ctarank;" : "=r"(rank));

    const float* xw = (dir == 0) ? g_xw_a : g_xw_b;
    const float* Ut = g_Ut[layer * 2 + dir];
    float* out = (layer == 0) ? g_v : g_hcat;
    const int coloff = dir * LL;          // concat column offset

    const int tid  = threadIdx.x;
    const int warp = tid >> 5, lane = tid & 31;
    const int usub = lane >> 3, sl = lane & 7;
    const int u = rank * 32 + warp * 4 + usub;  // hidden unit owned by this lane-group
    const bool prod = (sl == 0);                // lanes 0,8,16,24

    __shared__ __align__(16) float h_s[2][LL];
    __shared__ __align__(8) unsigned long long mbar[2];

    // Load this thread's U slice into registers: 4 gates x 8 float4 = 128 regs
    float4 Ug[4][8];
#pragma unroll
    for (int g = 0; g < 4; g++)
#pragma unroll
        for (int j = 0; j < 8; j++)
            Ug[g][j] = *(const float4*)&Ut[(g * LL + u) * LL + j * 32 + sl * 4];

    const uint32_t bar0 = smem_u32(&mbar[0]);
    const uint32_t bar1 = smem_u32(&mbar[1]);

    // init: zero h buffer 0, init barriers, post initial expects
    h_s[0][tid] = 0.f;
    if (tid == 0) {
        asm volatile("mbarrier.init.shared.b64 [%0], 1;" :: "r"(bar0) : "memory");
        asm volatile("mbarrier.init.shared.b64 [%0], 1;" :: "r"(bar1) : "memory");
        asm volatile("mbarrier.arrive.expect_tx.shared.b64 _, [%0], %1;" :: "r"(bar1), "r"(LL * 4) : "memory");
        asm volatile("mbarrier.arrive.expect_tx.shared.b64 _, [%0], %1;" :: "r"(bar0), "r"(LL * 4) : "memory");
    }
    __syncthreads();
    // barriers + zeroed h must be visible cluster-wide before any st.async lands
    asm volatile("barrier.cluster.arrive.aligned;" ::: "memory");
    asm volatile("barrier.cluster.wait.aligned;" ::: "memory");

    // hoisted DSMEM addressing: base = remote &h_s[0][u]; barrier/buffer deltas
    // are constant within-window offsets (mapa is offset-preserving).
    const uint32_t h0u = smem_u32(&h_s[0][u]);
    uint32_t dH0[CLU];
#pragma unroll
    for (int r = 0; r < CLU; r++)
        asm("mapa.shared::cluster.u32 %0, %1, %2;" : "=r"(dH0[r]) : "r"(h0u), "r"(r));
    const uint32_t offB0 = bar0 - h0u;
    const uint32_t offB1 = bar1 - h0u;
    const uint32_t offH1 = (uint32_t)(LL * 4);

    float c = 0.f;
    uint32_t ph0 = 0, ph1 = 0;   // phase parity per barrier

    // prefetch xw for the first token
    const int tok0 = (dir == 0) ? 0 : (TT - 1);
    float xwv0 = 0.f, xwv1 = 0.f, xwv2 = 0.f, xwv3 = 0.f;
    if (prod) {
        const float* xp = &xw[tok0 * ZDIM + u];
        xwv0 = __ldg(xp + 0 * LL);
        xwv1 = __ldg(xp + 1 * LL);
        xwv2 = __ldg(xp + 2 * LL);
        xwv3 = __ldg(xp + 3 * LL);
    }

    for (int s = 0; s < TT; s++) {
        if (s > 0) {
            const uint32_t b = (s & 1) ? bar1 : bar0;
            uint32_t& ph = (s & 1) ? ph1 : ph0;
            mbar_wait_parity(b, ph);
            ph ^= 1;
            // re-arm this barrier for its next use (step s+2); ordering vs the
            // remote tx it will count is enforced by the __syncthreads below.
            if (tid == 0)
                asm volatile("mbarrier.arrive.expect_tx.shared.b64 _, [%0], %1;" :: "r"(b), "r"(LL * 4) : "memory");
        }
        __syncthreads();

        const float* hc = h_s[s & 1];
        const int tok = (dir == 0) ? s : (TT - 1 - s);

        float acc0 = 0.f, acc1 = 0.f, acc2 = 0.f, acc3 = 0.f;
#pragma unroll
        for (int j = 0; j < 8; j++) {
            float4 h4 = *(const float4*)&hc[j * 32 + sl * 4];
            float4 a;
            a = Ug[0][j]; acc0 += a.x * h4.x + a.y * h4.y + a.z * h4.z + a.w * h4.w;
            a = Ug[1][j]; acc1 += a.x * h4.x + a.y * h4.y + a.z * h4.z + a.w * h4.w;
            a = Ug[2][j]; acc2 += a.x * h4.x + a.y * h4.y + a.z * h4.z + a.w * h4.w;
            a = Ug[3][j]; acc3 += a.x * h4.x + a.y * h4.y + a.z * h4.z + a.w * h4.w;
        }
        // reduce across the 8 slices of this unit (lanes usub*8 .. usub*8+7)
#pragma unroll
        for (int off = 4; off; off >>= 1) {
            acc0 += __shfl_down_sync(0xffffffffu, acc0, off, 8);
            acc1 += __shfl_down_sync(0xffffffffu, acc1, off, 8);
            acc2 += __shfl_down_sync(0xffffffffu, acc2, off, 8);
            acc3 += __shfl_down_sync(0xffffffffu, acc3, off, 8);
        }

        if (prod) {
            float iv = fsig(acc0 + xwv0);
            float fv = fsig(acc1 + xwv1);
            float gv = ftanh(acc2 + xwv2);
            float ov = fsig(acc3 + xwv3);
            c = fv * c + iv * gv;
            float hv = ov * ftanh(c);

            out[tok * (2 * LL) + coloff + u] = hv;

            if (s + 1 < TT) {
                // push h to next-step buffer + barrier in all 8 CTAs
                const uint32_t q = (s + 1) & 1;
                const uint32_t offH = q ? offH1 : 0u;
                const uint32_t offB = q ? offB1 : offB0;
                const uint32_t bits = __float_as_uint(hv);
#pragma unroll
                for (int r = 0; r < CLU; r++) {
                    asm volatile(
                        "st.async.shared::cluster.mbarrier::complete_tx::bytes.b32 [%0], %1, [%2];"
                        :: "r"(dH0[r] + offH), "r"(bits), "r"(dH0[r] + offB) : "memory");
                }
                // prefetch next token's xw while the cluster syncs
                const int ntok = (dir == 0) ? (s + 1) : (TT - 2 - s);
                const float* xp = &xw[ntok * ZDIM + u];
                xwv0 = __ldg(xp + 0 * LL);
                xwv1 = __ldg(xp + 1 * LL);
                xwv2 = __ldg(xp + 2 * LL);
                xwv3 = __ldg(xp + 3 * LL);
            }
        }
    }

    // hygiene: no CTA exits while peers could still address its SMEM
    asm volatile("barrier.cluster.arrive.aligned;" ::: "memory");
    asm volatile("barrier.cluster.wait.aligned;" ::: "memory");
}

// ---------------- pairwise head: out[i,j] = sum_h w[h]*tanh(hf[i,h]+mf[j,h]) + ob ----------------
__global__ void __launch_bounds__(256) pairwise_kernel(
    const float* __restrict__ headf, const float* __restrict__ modf,
    const float* __restrict__ outW, const float* __restrict__ outB,
    float* __restrict__ out) {
    __shared__ __align__(16) float SH[32][132];
    __shared__ float SMt[128][33];
    __shared__ __align__(16) float Wsh[128];

    const int t = threadIdx.x;
    const int i0 = blockIdx.y * 32, j0 = blockIdx.x * 32;
    const int li = t >> 3;
    const int lj = (t & 7) * 4;

    float acc0 = 0.f, acc1 = 0.f, acc2 = 0.f, acc3 = 0.f;

    for (int hc = 0; hc < HH; hc += 128) {
#pragma unroll
        for (int r = 0; r < 4; r++) {
            int idx = t + r * 256;
            int row = idx >> 5;
            int c4 = (idx & 31) * 4;
            float4 hvv = *(const float4*)&headf[(i0 + row) * HH + hc + c4];
            *(float4*)&SH[row][c4] = hvv;
            float4 mvv = *(const float4*)&modf[(j0 + row) * HH + hc + c4];
            SMt[c4 + 0][row] = mvv.x; SMt[c4 + 1][row] = mvv.y;
            SMt[c4 + 2][row] = mvv.z; SMt[c4 + 3][row] = mvv.w;
        }
        if (t < 32) *(float4*)&Wsh[t * 4] = *(const float4*)&outW[hc + t * 4];
        __syncthreads();

#pragma unroll 4
        for (int h = 0; h < 128; h++) {
            float hv = SH[li][h];
            float w = Wsh[h];
            acc0 += w * ftanh_hw(hv + SMt[h][lj + 0]);
            acc1 += w * ftanh_hw(hv + SMt[h][lj + 1]);
            acc2 += w * ftanh_hw(hv + SMt[h][lj + 2]);
            acc3 += w * ftanh_hw(hv + SMt[h][lj + 3]);
        }
        __syncthreads();
    }

    const float ob = outB[0];
    float* orow = &out[(i0 + li) * TT + j0 + lj];
    orow[0] = acc0 + ob;
    orow[1] = acc1 + ob;
    orow[2] = acc2 + ob;
    orow[3] = acc3 + ob;
}

// ---------------- host side ----------------
extern "C" void kernel_launch(void* const* d_in, const int* in_sizes, int n_in,
                              void* d_out, int out_size) {
    (void)in_sizes; (void)n_in; (void)out_size;
    const float* emb     = (const float*)d_in[0];
    const float* W_f1    = (const float*)d_in[1];
    const float* U_f1    = (const float*)d_in[2];
    const float* b_f1    = (const float*)d_in[3];
    const float* W_b1    = (const float*)d_in[4];
    const float* U_b1    = (const float*)d_in[5];
    const float* b_b1    = (const float*)d_in[6];
    const float* W_f2    = (const float*)d_in[7];
    const float* U_f2    = (const float*)d_in[8];
    const float* b_f2    = (const float*)d_in[9];
    const float* W_b2    = (const float*)d_in[10];
    const float* U_b2    = (const float*)d_in[11];
    const float* b_b2    = (const float*)d_in[12];
    const float* FOH     = (const float*)d_in[13];
    const float* FOM     = (const float*)d_in[14];
    const float* hidBias = (const float*)d_in[15];
    const float* outW    = (const float*)d_in[16];
    const float* outBias = (const float*)d_in[17];

    float *xwa, *xwb, *v, *hcat, *headf, *modf;
    cudaGetSymbolAddress((void**)&xwa,   g_xw_a);
    cudaGetSymbolAddress((void**)&xwb,   g_xw_b);
    cudaGetSymbolAddress((void**)&v,     g_v);
    cudaGetSymbolAddress((void**)&hcat,  g_hcat);
    cudaGetSymbolAddress((void**)&headf, g_headf);
    cudaGetSymbolAddress((void**)&modf,  g_modf);

    // 1. transpose all recurrent matrices
    transposeU_kernel<<<dim3(ZDIM / 32, LL / 32, 4), dim3(32, 8)>>>(U_f1, U_b1, U_f2, U_b2);

    // 2. layer-1 input projections (both directions, bias folded in)
    gemm2_kernel<<<dim3(ZDIM / 64, TT / 64, 2), 256>>>(
        emb, emb, W_f1, W_b1, b_f1, b_b1, xwa, xwb, TT, ZDIM, DD);

    // 3. layer-1 BiLSTM (fw + bw clusters concurrently), writes concat layout -> v
    lstm_cluster_kernel<<<2 * CLU, 256>>>(0);

    // 4. layer-2 input projections
    gemm2_kernel<<<dim3(ZDIM / 64, TT / 64, 2), 256>>>(
        v, v, W_f2, W_b2, b_f2, b_b2, xwa, xwb, TT, ZDIM, 2 * LL);

    // 5. layer-2 BiLSTM -> hcat
    lstm_cluster_kernel<<<2 * CLU, 256>>>(1);

    // 6. head projections (hidBias folded into headfov)
    gemm2_kernel<<<dim3(HH / 64, TT / 64, 2), 256>>>(
        hcat, hcat, FOH, FOM, hidBias, nullptr, headf, modf, TT, HH, 2 * LL);

    // 7. pairwise scores
    pairwise_kernel<<<dim3(TT / 32, TT / 32), 256>>>(headf, modf, outW, outBias, (float*)d_out);
}